// round 2
// baseline (speedup 1.0000x reference)
#include <cuda_runtime.h>
#include <cuda_bf16.h>
#include <math.h>

#define S 4096
#define D 512
#define F 2048
#define H 8
#define DH 64
#define EPS 1e-5f

// ---------------- scratch (static device globals; no allocation allowed) ----
__device__ float g_q[S * D];
__device__ float g_k[S * D];
__device__ float g_v[S * D];
__device__ float g_attn[S * D];
__device__ float g_proj[S * D];   // reused: attn proj out, then ff2 out
__device__ float g_x1[S * D];     // after first LN
__device__ float g_ff[S * F];
__device__ float g_scores[(size_t)H * S * S];  // 512 MB

// ---------------- generic batched tiled GEMM --------------------------------
// C[bz] = A[bz] @ (B[bz] or B[bz]^T) (+bias) (+relu)
// BM=BN=64, BK=16, 256 threads, 4x4 micro-tile per thread.
// All dims assumed multiples of tile sizes (they are for this problem).
template <bool TRANSB, bool HASBIAS, bool RELU>
__global__ void __launch_bounds__(256) gemm_k(
    const float* __restrict__ A, const float* __restrict__ B,
    const float* __restrict__ bias, float* __restrict__ C,
    int M, int N, int K, int lda, int ldb, int ldc,
    long long sA, long long sB, long long sC)
{
    const int bz = blockIdx.z;
    A += (long long)bz * sA;
    B += (long long)bz * sB;
    C += (long long)bz * sC;

    const int m0 = blockIdx.y * 64;
    const int n0 = blockIdx.x * 64;
    const int t  = threadIdx.x;

    __shared__ float As[16][64];
    __shared__ float Bs[16][64];

    // A-load mapping: each thread loads one float4 along K
    const int m_a = t >> 2;            // 0..63
    const int k_a = (t & 3) * 4;       // 0,4,8,12
    // B NN-load mapping
    const int k_b = t >> 4;            // 0..15
    const int n_b = (t & 15) * 4;      // 0..60

    const int ty = t >> 4;             // 0..15 -> m sub-tile
    const int tx = t & 15;             // 0..15 -> n sub-tile

    float acc[4][4];
#pragma unroll
    for (int i = 0; i < 4; i++)
#pragma unroll
        for (int j = 0; j < 4; j++) acc[i][j] = 0.f;

    for (int k0 = 0; k0 < K; k0 += 16) {
        float4 av = *(const float4*)(A + (long long)(m0 + m_a) * lda + k0 + k_a);
        As[k_a + 0][m_a] = av.x;
        As[k_a + 1][m_a] = av.y;
        As[k_a + 2][m_a] = av.z;
        As[k_a + 3][m_a] = av.w;

        if (TRANSB) {
            // B is N x K row-major; Bs[k][n] = B[n][k]
            float4 bv = *(const float4*)(B + (long long)(n0 + m_a) * ldb + k0 + k_a);
            Bs[k_a + 0][m_a] = bv.x;
            Bs[k_a + 1][m_a] = bv.y;
            Bs[k_a + 2][m_a] = bv.z;
            Bs[k_a + 3][m_a] = bv.w;
        } else {
            float4 bv = *(const float4*)(B + (long long)(k0 + k_b) * ldb + n0 + n_b);
            *(float4*)&Bs[k_b][n_b] = bv;
        }
        __syncthreads();

#pragma unroll
        for (int kk = 0; kk < 16; kk++) {
            float4 a = *(const float4*)&As[kk][ty * 4];
            float4 b = *(const float4*)&Bs[kk][tx * 4];
            float ar[4] = {a.x, a.y, a.z, a.w};
            float br[4] = {b.x, b.y, b.z, b.w};
#pragma unroll
            for (int i = 0; i < 4; i++)
#pragma unroll
                for (int j = 0; j < 4; j++)
                    acc[i][j] = fmaf(ar[i], br[j], acc[i][j]);
        }
        __syncthreads();
    }

#pragma unroll
    for (int i = 0; i < 4; i++) {
        const int m = m0 + ty * 4 + i;
        float4 v;
        float* vv = (float*)&v;
#pragma unroll
        for (int j = 0; j < 4; j++) {
            float x = acc[i][j];
            if (HASBIAS) x += bias[n0 + tx * 4 + j];
            if (RELU)    x = fmaxf(x, 0.f);
            vv[j] = x;
        }
        *(float4*)(C + (long long)m * ldc + n0 + tx * 4) = v;
    }
}

// ---------------- masked softmax over rows of scores -------------------------
// grid: (S rows, H heads), block 256. Each thread caches 16 elements.
__global__ void __launch_bounds__(256) softmax_mask_k(
    float* __restrict__ scores, const int* __restrict__ mask)
{
    const int row = blockIdx.x;
    const int h   = blockIdx.y;
    float* p = scores + ((size_t)h * S + row) * S;
    const int* m = mask + (size_t)row * S;
    const int t = threadIdx.x;

    float v[16];
#pragma unroll
    for (int i = 0; i < 16; i++) {
        int j = t + i * 256;
        v[i] = (m[j] != 0) ? p[j] : -1e9f;
    }

    // block max
    float mx = v[0];
#pragma unroll
    for (int i = 1; i < 16; i++) mx = fmaxf(mx, v[i]);
    __shared__ float red[8];
#pragma unroll
    for (int o = 16; o > 0; o >>= 1) mx = fmaxf(mx, __shfl_xor_sync(0xffffffffu, mx, o));
    if ((t & 31) == 0) red[t >> 5] = mx;
    __syncthreads();
    if (t < 8) {
        float r = red[t];
#pragma unroll
        for (int o = 4; o > 0; o >>= 1) r = fmaxf(r, __shfl_xor_sync(0xffu, r, o));
        if (t == 0) red[0] = r;
    }
    __syncthreads();
    mx = red[0];
    __syncthreads();

    // exp + sum
    float sum = 0.f;
#pragma unroll
    for (int i = 0; i < 16; i++) {
        v[i] = expf(v[i] - mx);
        sum += v[i];
    }
#pragma unroll
    for (int o = 16; o > 0; o >>= 1) sum += __shfl_xor_sync(0xffffffffu, sum, o);
    if ((t & 31) == 0) red[t >> 5] = sum;
    __syncthreads();
    if (t < 8) {
        float r = red[t];
#pragma unroll
        for (int o = 4; o > 0; o >>= 1) r += __shfl_xor_sync(0xffu, r, o);
        if (t == 0) red[0] = r;
    }
    __syncthreads();
    const float inv = 1.f / red[0];

#pragma unroll
    for (int i = 0; i < 16; i++) p[t + i * 256] = v[i] * inv;
}

// ---------------- fused residual add + LayerNorm -----------------------------
// grid: S rows, block 256 (2 elements per thread, D=512)
__global__ void __launch_bounds__(256) add_ln_k(
    const float* __restrict__ x, const float* __restrict__ r,
    const float* __restrict__ g, const float* __restrict__ b,
    float* __restrict__ y)
{
    const int row = blockIdx.x;
    const int t   = threadIdx.x;
    const long long base = (long long)row * D;

    float v0 = x[base + t]       + r[base + t];
    float v1 = x[base + t + 256] + r[base + t + 256];

    float s  = v0 + v1;
    float s2 = v0 * v0 + v1 * v1;

    __shared__ float rs[8], rs2[8];
#pragma unroll
    for (int o = 16; o > 0; o >>= 1) {
        s  += __shfl_xor_sync(0xffffffffu, s, o);
        s2 += __shfl_xor_sync(0xffffffffu, s2, o);
    }
    if ((t & 31) == 0) { rs[t >> 5] = s; rs2[t >> 5] = s2; }
    __syncthreads();
    if (t < 8) {
        float a = rs[t], c = rs2[t];
#pragma unroll
        for (int o = 4; o > 0; o >>= 1) {
            a += __shfl_xor_sync(0xffu, a, o);
            c += __shfl_xor_sync(0xffu, c, o);
        }
        if (t == 0) { rs[0] = a; rs2[0] = c; }
    }
    __syncthreads();
    const float mu  = rs[0] * (1.f / D);
    const float var = rs2[0] * (1.f / D) - mu * mu;
    const float rstd = rsqrtf(var + EPS);

    y[base + t]       = (v0 - mu) * rstd * g[t]       + b[t];
    y[base + t + 256] = (v1 - mu) * rstd * g[t + 256] + b[t + 256];
}

// ---------------- launch -----------------------------------------------------
extern "C" void kernel_launch(void* const* d_in, const int* in_sizes, int n_in,
                              void* d_out, int out_size)
{
    const float* x    = (const float*)d_in[0];
    const int*   mask = (const int*)  d_in[1];
    const float* wq   = (const float*)d_in[2];
    const float* bq   = (const float*)d_in[3];
    const float* wk   = (const float*)d_in[4];
    const float* bk   = (const float*)d_in[5];
    const float* wv   = (const float*)d_in[6];
    const float* bv   = (const float*)d_in[7];
    const float* wo   = (const float*)d_in[8];
    const float* bo   = (const float*)d_in[9];
    const float* w1   = (const float*)d_in[10];
    const float* b1   = (const float*)d_in[11];
    const float* w2   = (const float*)d_in[12];
    const float* b2   = (const float*)d_in[13];
    const float* g1   = (const float*)d_in[14];
    const float* be1  = (const float*)d_in[15];
    const float* g2   = (const float*)d_in[16];
    const float* be2  = (const float*)d_in[17];
    float* out = (float*)d_out;

    float *q, *k, *v, *attn, *proj, *x1, *ff, *sc;
    cudaGetSymbolAddress((void**)&q,    g_q);
    cudaGetSymbolAddress((void**)&k,    g_k);
    cudaGetSymbolAddress((void**)&v,    g_v);
    cudaGetSymbolAddress((void**)&attn, g_attn);
    cudaGetSymbolAddress((void**)&proj, g_proj);
    cudaGetSymbolAddress((void**)&x1,   g_x1);
    cudaGetSymbolAddress((void**)&ff,   g_ff);
    cudaGetSymbolAddress((void**)&sc,   g_scores);

    const dim3 blk(256);

    // QKV projections: (S,D) @ (D,D) + bias
    {
        dim3 grid(D / 64, S / 64, 1);
        gemm_k<false, true, false><<<grid, blk>>>(x, wq, bq, q, S, D, D, D, D, D, 0, 0, 0);
        gemm_k<false, true, false><<<grid, blk>>>(x, wk, bk, k, S, D, D, D, D, D, 0, 0, 0);
        gemm_k<false, true, false><<<grid, blk>>>(x, wv, bv, v, S, D, D, D, D, D, 0, 0, 0);
    }

    // scores[h] = Q_h @ K_h^T  (M=S, N=S, K=DH), head-batched via grid.z
    {
        dim3 grid(S / 64, S / 64, H);
        gemm_k<true, false, false><<<grid, blk>>>(q, k, nullptr, sc,
            S, S, DH, D, D, S, DH, DH, (long long)S * S);
    }

    // masked softmax
    softmax_mask_k<<<dim3(S, H), blk>>>(sc, mask);

    // attn_h = P_h @ V_h  (M=S, N=DH, K=S)
    {
        dim3 grid(DH / 64, S / 64, H);
        gemm_k<false, false, false><<<grid, blk>>>(sc, v, nullptr, attn,
            S, DH, S, S, D, D, (long long)S * S, DH, DH);
    }

    // output projection
    {
        dim3 grid(D / 64, S / 64, 1);
        gemm_k<false, true, false><<<grid, blk>>>(attn, wo, bo, proj, S, D, D, D, D, D, 0, 0, 0);
    }

    // x1 = LN(x + proj)
    add_ln_k<<<S, blk>>>(x, proj, g1, be1, x1);

    // ff = relu(x1 @ w1 + b1)
    {
        dim3 grid(F / 64, S / 64, 1);
        gemm_k<false, true, true><<<grid, blk>>>(x1, w1, b1, ff, S, F, D, D, F, F, 0, 0, 0);
    }

    // ff2 = ff @ w2 + b2  (reuse proj)
    {
        dim3 grid(D / 64, S / 64, 1);
        gemm_k<false, true, false><<<grid, blk>>>(ff, w2, b2, proj, S, D, F, F, D, D, 0, 0, 0);
    }

    // out = LN(x1 + ff2)
    add_ln_k<<<S, blk>>>(x1, proj, g2, be2, out);
}

// round 3
// speedup vs baseline: 1.9296x; 1.9296x over previous
#include <cuda_runtime.h>
#include <cuda_bf16.h>
#include <math.h>

#define S 4096
#define D 512
#define F 2048
#define H 8
#define DH 64
#define EPS 1e-5f

typedef __nv_bfloat16 bf;

// ---------------- scratch (static device globals) ---------------------------
__device__ bf g_xhi[S * D], g_xlo[S * D];
__device__ bf g_wqThi[D * D], g_wqTlo[D * D];
__device__ bf g_wkThi[D * D], g_wkTlo[D * D];
__device__ bf g_wvThi[D * D], g_wvTlo[D * D];
__device__ bf g_woThi[D * D], g_woTlo[D * D];
__device__ bf g_w1Thi[(size_t)F * D], g_w1Tlo[(size_t)F * D];
__device__ bf g_w2Thi[(size_t)D * F], g_w2Tlo[(size_t)D * F];
__device__ bf g_qhi[S * D], g_qlo[S * D];
__device__ bf g_khi[S * D], g_klo[S * D];
__device__ float g_vf[S * D];
__device__ bf g_vThi[(size_t)D * S], g_vTlo[(size_t)D * S];
__device__ float g_scores[(size_t)H * S * S];                 // 512 MB
__device__ bf g_Phi[(size_t)H * S * S], g_Plo[(size_t)H * S * S]; // 256+256 MB
__device__ bf g_attnhi[S * D], g_attnlo[S * D];
__device__ float g_proj[S * D];
__device__ float g_x1[S * D];
__device__ bf g_x1hi[S * D], g_x1lo[S * D];
__device__ bf g_ffhi[(size_t)S * F], g_fflo[(size_t)S * F];

// ---------------- helpers ----------------------------------------------------
__device__ __forceinline__ void split2(float v, bf& h, bf& l) {
    h = __float2bfloat16(v);
    l = __float2bfloat16(v - __bfloat162float(h));
}

#define MMA_BF16(c, a, b) asm volatile( \
    "mma.sync.aligned.m16n8k16.row.col.f32.bf16.bf16.f32 " \
    "{%0,%1,%2,%3}, {%4,%5,%6,%7}, {%8,%9}, {%0,%1,%2,%3};\n" \
    : "+f"((c)[0]), "+f"((c)[1]), "+f"((c)[2]), "+f"((c)[3]) \
    : "r"((a)[0]), "r"((a)[1]), "r"((a)[2]), "r"((a)[3]), \
      "r"((b)[0]), "r"((b)[1]))

// ---------------- split fp32 -> (hi, lo) bf16 --------------------------------
__global__ void __launch_bounds__(256) split_k(
    const float4* __restrict__ in, __nv_bfloat162* __restrict__ hi2,
    __nv_bfloat162* __restrict__ lo2, int n4)
{
    int i = blockIdx.x * 256 + threadIdx.x;
    if (i >= n4) return;
    float4 v = in[i];
    bf hx, lx, hy, ly, hz, lz, hw, lw;
    split2(v.x, hx, lx); split2(v.y, hy, ly);
    split2(v.z, hz, lz); split2(v.w, hw, lw);
    __nv_bfloat162 a, b;
    a.x = hx; a.y = hy; b.x = hz; b.y = hw;
    hi2[2 * i] = a; hi2[2 * i + 1] = b;
    a.x = lx; a.y = ly; b.x = lz; b.y = lw;
    lo2[2 * i] = a; lo2[2 * i + 1] = b;
}

// ---------------- transpose + split: in[R][C] fp32 -> out[C][R] hi/lo --------
__global__ void __launch_bounds__(256) tsplit_k(
    const float* __restrict__ in, bf* __restrict__ hi, bf* __restrict__ lo,
    int R, int C)
{
    __shared__ float tile[32][33];
    const int c0 = blockIdx.x * 32, r0 = blockIdx.y * 32;
    const int tx = threadIdx.x & 31, ty = threadIdx.x >> 5;
#pragma unroll
    for (int rr = ty; rr < 32; rr += 8)
        tile[rr][tx] = in[(long long)(r0 + rr) * C + c0 + tx];
    __syncthreads();
#pragma unroll
    for (int cc = ty; cc < 32; cc += 8) {
        float v = tile[tx][cc];
        bf h, l; split2(v, h, l);
        long long o = (long long)(c0 + cc) * R + r0 + tx;
        hi[o] = h; lo[o] = l;
    }
}

// ---------------- bf16x3 tensor-core GEMM (NT form) --------------------------
// C[m][n] = sum_k A[m][k] * BT[n][k], A/BT given as (hi,lo) bf16 pairs.
// Block tile 128x64, BK=32, 256 threads (8 warps: 4 in M x 2 in N).
template <bool HASBIAS, bool RELU, bool SPLITOUT>
__global__ void __launch_bounds__(256) gemm3_k(
    const bf* __restrict__ Ahi, const bf* __restrict__ Alo,
    const bf* __restrict__ Bhi, const bf* __restrict__ Blo,
    const float* __restrict__ bias,
    float* __restrict__ C, bf* __restrict__ Chi, bf* __restrict__ Clo,
    int K, int lda, int ldb, int ldc,
    long long aOff, long long bOff, long long cOff)
{
    const int bz = blockIdx.z;
    Ahi += (long long)bz * aOff; Alo += (long long)bz * aOff;
    Bhi += (long long)bz * bOff; Blo += (long long)bz * bOff;
    const long long cbase = (long long)bz * cOff;

    const int m0 = blockIdx.y * 128;
    const int n0 = blockIdx.x * 64;
    const int t = threadIdx.x;
    const int lane = t & 31, warp = t >> 5;
    const int g = lane >> 2, ctid = lane & 3;
    const int wm = (warp & 3) * 32;
    const int wn = (warp >> 2) * 32;

    __shared__ __align__(16) bf Ahs[128 * 40];
    __shared__ __align__(16) bf Als[128 * 40];
    __shared__ __align__(16) bf Bhs[64 * 40];
    __shared__ __align__(16) bf Bls[64 * 40];

    float acc[2][4][4];
#pragma unroll
    for (int i = 0; i < 2; i++)
#pragma unroll
        for (int j = 0; j < 4; j++)
#pragma unroll
            for (int r = 0; r < 4; r++) acc[i][j][r] = 0.f;

    const int ar = t >> 2;         // 0..63
    const int ac = (t & 3) * 8;    // 0,8,16,24

    for (int k0 = 0; k0 < K; k0 += 32) {
        const bf* pAh = Ahi + (long long)(m0 + ar) * lda + k0 + ac;
        const bf* pAl = Alo + (long long)(m0 + ar) * lda + k0 + ac;
        *(uint4*)&Ahs[ar * 40 + ac] = *(const uint4*)pAh;
        *(uint4*)&Als[ar * 40 + ac] = *(const uint4*)pAl;
        *(uint4*)&Ahs[(ar + 64) * 40 + ac] = *(const uint4*)(pAh + (long long)64 * lda);
        *(uint4*)&Als[(ar + 64) * 40 + ac] = *(const uint4*)(pAl + (long long)64 * lda);
        *(uint4*)&Bhs[ar * 40 + ac] = *(const uint4*)(Bhi + (long long)(n0 + ar) * ldb + k0 + ac);
        *(uint4*)&Bls[ar * 40 + ac] = *(const uint4*)(Blo + (long long)(n0 + ar) * ldb + k0 + ac);
        __syncthreads();

#pragma unroll
        for (int ks = 0; ks < 2; ks++) {
            const int kb = ks * 16 + ctid * 2;
            unsigned int ah[2][4], al[2][4], bh[4][2], bl[4][2];
#pragma unroll
            for (int i = 0; i < 2; i++) {
                const int row = wm + i * 16 + g;
                ah[i][0] = *(const unsigned int*)&Ahs[row * 40 + kb];
                ah[i][1] = *(const unsigned int*)&Ahs[(row + 8) * 40 + kb];
                ah[i][2] = *(const unsigned int*)&Ahs[row * 40 + kb + 8];
                ah[i][3] = *(const unsigned int*)&Ahs[(row + 8) * 40 + kb + 8];
                al[i][0] = *(const unsigned int*)&Als[row * 40 + kb];
                al[i][1] = *(const unsigned int*)&Als[(row + 8) * 40 + kb];
                al[i][2] = *(const unsigned int*)&Als[row * 40 + kb + 8];
                al[i][3] = *(const unsigned int*)&Als[(row + 8) * 40 + kb + 8];
            }
#pragma unroll
            for (int j = 0; j < 4; j++) {
                const int nr = wn + j * 8 + g;
                bh[j][0] = *(const unsigned int*)&Bhs[nr * 40 + kb];
                bh[j][1] = *(const unsigned int*)&Bhs[nr * 40 + kb + 8];
                bl[j][0] = *(const unsigned int*)&Bls[nr * 40 + kb];
                bl[j][1] = *(const unsigned int*)&Bls[nr * 40 + kb + 8];
            }
#pragma unroll
            for (int i = 0; i < 2; i++)
#pragma unroll
                for (int j = 0; j < 4; j++) {
                    MMA_BF16(acc[i][j], ah[i], bh[j]);
                    MMA_BF16(acc[i][j], ah[i], bl[j]);
                    MMA_BF16(acc[i][j], al[i], bh[j]);
                }
        }
        __syncthreads();
    }

    // epilogue
#pragma unroll
    for (int i = 0; i < 2; i++) {
#pragma unroll
        for (int j = 0; j < 4; j++) {
            const int row0 = m0 + wm + i * 16 + g;
            const int col = n0 + wn + j * 8 + ctid * 2;
            float bia0 = 0.f, bia1 = 0.f;
            if (HASBIAS) { bia0 = bias[col]; bia1 = bias[col + 1]; }
#pragma unroll
            for (int hh = 0; hh < 2; hh++) {
                const int row = row0 + hh * 8;
                float v0 = acc[i][j][hh * 2 + 0] + bia0;
                float v1 = acc[i][j][hh * 2 + 1] + bia1;
                if (RELU) { v0 = fmaxf(v0, 0.f); v1 = fmaxf(v1, 0.f); }
                const long long o = cbase + (long long)row * ldc + col;
                if (SPLITOUT) {
                    bf h0, l0, h1, l1;
                    split2(v0, h0, l0); split2(v1, h1, l1);
                    __nv_bfloat162 ph, pl;
                    ph.x = h0; ph.y = h1; pl.x = l0; pl.y = l1;
                    *(__nv_bfloat162*)&Chi[o] = ph;
                    *(__nv_bfloat162*)&Clo[o] = pl;
                } else {
                    *(float2*)&C[o] = make_float2(v0, v1);
                }
            }
        }
    }
}

// ---------------- masked softmax, writes hi/lo bf16 probs --------------------
__global__ void __launch_bounds__(256) softmax_mask_split_k(
    const float* __restrict__ scores, const int* __restrict__ mask,
    bf* __restrict__ Phi, bf* __restrict__ Plo)
{
    const int row = blockIdx.x;
    const int h = blockIdx.y;
    const size_t base = ((size_t)h * S + row) * S;
    const float* p = scores + base;
    const int* m = mask + (size_t)row * S;
    const int t = threadIdx.x;

    float v[16];
#pragma unroll
    for (int i = 0; i < 16; i++) {
        int j = t + i * 256;
        v[i] = (m[j] != 0) ? p[j] : -1e9f;
    }

    float mx = v[0];
#pragma unroll
    for (int i = 1; i < 16; i++) mx = fmaxf(mx, v[i]);
    __shared__ float red[8];
#pragma unroll
    for (int o = 16; o > 0; o >>= 1) mx = fmaxf(mx, __shfl_xor_sync(0xffffffffu, mx, o));
    if ((t & 31) == 0) red[t >> 5] = mx;
    __syncthreads();
    if (t < 8) {
        float r = red[t];
#pragma unroll
        for (int o = 4; o > 0; o >>= 1) r = fmaxf(r, __shfl_xor_sync(0xffu, r, o));
        if (t == 0) red[0] = r;
    }
    __syncthreads();
    mx = red[0];
    __syncthreads();

    float sum = 0.f;
#pragma unroll
    for (int i = 0; i < 16; i++) {
        v[i] = expf(v[i] - mx);
        sum += v[i];
    }
#pragma unroll
    for (int o = 16; o > 0; o >>= 1) sum += __shfl_xor_sync(0xffffffffu, sum, o);
    if ((t & 31) == 0) red[t >> 5] = sum;
    __syncthreads();
    if (t < 8) {
        float r = red[t];
#pragma unroll
        for (int o = 4; o > 0; o >>= 1) r += __shfl_xor_sync(0xffu, r, o);
        if (t == 0) red[0] = r;
    }
    __syncthreads();
    const float inv = 1.f / red[0];

#pragma unroll
    for (int i = 0; i < 16; i++) {
        float pr = v[i] * inv;
        bf hh, ll; split2(pr, hh, ll);
        Phi[base + t + i * 256] = hh;
        Plo[base + t + i * 256] = ll;
    }
}

// ---------------- fused residual add + LayerNorm (+optional split) -----------
template <bool SPLIT>
__global__ void __launch_bounds__(256) add_ln_k(
    const float* __restrict__ x, const float* __restrict__ r,
    const float* __restrict__ g, const float* __restrict__ b,
    float* __restrict__ y, bf* __restrict__ yhi, bf* __restrict__ ylo)
{
    const int row = blockIdx.x;
    const int t = threadIdx.x;
    const long long base = (long long)row * D;

    float v0 = x[base + t] + r[base + t];
    float v1 = x[base + t + 256] + r[base + t + 256];

    float s = v0 + v1;
    float s2 = v0 * v0 + v1 * v1;

    __shared__ float rs[8], rs2[8];
#pragma unroll
    for (int o = 16; o > 0; o >>= 1) {
        s += __shfl_xor_sync(0xffffffffu, s, o);
        s2 += __shfl_xor_sync(0xffffffffu, s2, o);
    }
    if ((t & 31) == 0) { rs[t >> 5] = s; rs2[t >> 5] = s2; }
    __syncthreads();
    if (t < 8) {
        float a = rs[t], c = rs2[t];
#pragma unroll
        for (int o = 4; o > 0; o >>= 1) {
            a += __shfl_xor_sync(0xffu, a, o);
            c += __shfl_xor_sync(0xffu, c, o);
        }
        if (t == 0) { rs[0] = a; rs2[0] = c; }
    }
    __syncthreads();
    const float mu = rs[0] * (1.f / D);
    const float var = rs2[0] * (1.f / D) - mu * mu;
    const float rstd = rsqrtf(var + EPS);

    float y0 = (v0 - mu) * rstd * g[t] + b[t];
    float y1 = (v1 - mu) * rstd * g[t + 256] + b[t + 256];
    y[base + t] = y0;
    y[base + t + 256] = y1;
    if (SPLIT) {
        bf h0, l0, h1, l1;
        split2(y0, h0, l0); split2(y1, h1, l1);
        yhi[base + t] = h0; ylo[base + t] = l0;
        yhi[base + t + 256] = h1; ylo[base + t + 256] = l1;
    }
}

// ---------------- launch -----------------------------------------------------
extern "C" void kernel_launch(void* const* d_in, const int* in_sizes, int n_in,
                              void* d_out, int out_size)
{
    const float* x   = (const float*)d_in[0];
    const int* mask  = (const int*)d_in[1];
    const float* wq  = (const float*)d_in[2];
    const float* bq  = (const float*)d_in[3];
    const float* wk  = (const float*)d_in[4];
    const float* bk  = (const float*)d_in[5];
    const float* wv  = (const float*)d_in[6];
    const float* bv  = (const float*)d_in[7];
    const float* wo  = (const float*)d_in[8];
    const float* bo  = (const float*)d_in[9];
    const float* w1  = (const float*)d_in[10];
    const float* b1  = (const float*)d_in[11];
    const float* w2  = (const float*)d_in[12];
    const float* b2  = (const float*)d_in[13];
    const float* g1  = (const float*)d_in[14];
    const float* be1 = (const float*)d_in[15];
    const float* g2  = (const float*)d_in[16];
    const float* be2 = (const float*)d_in[17];
    float* out = (float*)d_out;

    bf *xhi, *xlo, *wqThi, *wqTlo, *wkThi, *wkTlo, *wvThi, *wvTlo, *woThi, *woTlo;
    bf *w1Thi, *w1Tlo, *w2Thi, *w2Tlo, *qhi, *qlo, *khi, *klo, *vThi, *vTlo;
    bf *Phi, *Plo, *attnhi, *attnlo, *x1hi, *x1lo, *ffhi, *fflo;
    float *vf, *sc, *proj, *x1;
    cudaGetSymbolAddress((void**)&xhi, g_xhi);   cudaGetSymbolAddress((void**)&xlo, g_xlo);
    cudaGetSymbolAddress((void**)&wqThi, g_wqThi); cudaGetSymbolAddress((void**)&wqTlo, g_wqTlo);
    cudaGetSymbolAddress((void**)&wkThi, g_wkThi); cudaGetSymbolAddress((void**)&wkTlo, g_wkTlo);
    cudaGetSymbolAddress((void**)&wvThi, g_wvThi); cudaGetSymbolAddress((void**)&wvTlo, g_wvTlo);
    cudaGetSymbolAddress((void**)&woThi, g_woThi); cudaGetSymbolAddress((void**)&woTlo, g_woTlo);
    cudaGetSymbolAddress((void**)&w1Thi, g_w1Thi); cudaGetSymbolAddress((void**)&w1Tlo, g_w1Tlo);
    cudaGetSymbolAddress((void**)&w2Thi, g_w2Thi); cudaGetSymbolAddress((void**)&w2Tlo, g_w2Tlo);
    cudaGetSymbolAddress((void**)&qhi, g_qhi);   cudaGetSymbolAddress((void**)&qlo, g_qlo);
    cudaGetSymbolAddress((void**)&khi, g_khi);   cudaGetSymbolAddress((void**)&klo, g_klo);
    cudaGetSymbolAddress((void**)&vf, g_vf);
    cudaGetSymbolAddress((void**)&vThi, g_vThi); cudaGetSymbolAddress((void**)&vTlo, g_vTlo);
    cudaGetSymbolAddress((void**)&sc, g_scores);
    cudaGetSymbolAddress((void**)&Phi, g_Phi);   cudaGetSymbolAddress((void**)&Plo, g_Plo);
    cudaGetSymbolAddress((void**)&attnhi, g_attnhi); cudaGetSymbolAddress((void**)&attnlo, g_attnlo);
    cudaGetSymbolAddress((void**)&proj, g_proj);
    cudaGetSymbolAddress((void**)&x1, g_x1);
    cudaGetSymbolAddress((void**)&x1hi, g_x1hi); cudaGetSymbolAddress((void**)&x1lo, g_x1lo);
    cudaGetSymbolAddress((void**)&ffhi, g_ffhi); cudaGetSymbolAddress((void**)&fflo, g_fflo);

    const dim3 blk(256);

    // split x
    split_k<<<(S * D / 4 + 255) / 256, blk>>>((const float4*)x,
        (__nv_bfloat162*)xhi, (__nv_bfloat162*)xlo, S * D / 4);

    // transpose + split weights
    tsplit_k<<<dim3(D / 32, D / 32), blk>>>(wq, wqThi, wqTlo, D, D);
    tsplit_k<<<dim3(D / 32, D / 32), blk>>>(wk, wkThi, wkTlo, D, D);
    tsplit_k<<<dim3(D / 32, D / 32), blk>>>(wv, wvThi, wvTlo, D, D);
    tsplit_k<<<dim3(D / 32, D / 32), blk>>>(wo, woThi, woTlo, D, D);
    tsplit_k<<<dim3(F / 32, D / 32), blk>>>(w1, w1Thi, w1Tlo, D, F);  // [D][F] -> [F][D]
    tsplit_k<<<dim3(D / 32, F / 32), blk>>>(w2, w2Thi, w2Tlo, F, D);  // [F][D] -> [D][F]

    // QKV projections: (S,D)@(D,D)+bias  -> q,k split-out; v fp32
    {
        dim3 grid(D / 64, S / 128, 1);
        gemm3_k<true, false, true><<<grid, blk>>>(xhi, xlo, wqThi, wqTlo, bq,
            nullptr, qhi, qlo, D, D, D, D, 0, 0, 0);
        gemm3_k<true, false, true><<<grid, blk>>>(xhi, xlo, wkThi, wkTlo, bk,
            nullptr, khi, klo, D, D, D, D, 0, 0, 0);
        gemm3_k<true, false, false><<<grid, blk>>>(xhi, xlo, wvThi, wvTlo, bv,
            vf, nullptr, nullptr, D, D, D, D, 0, 0, 0);
    }

    // vT = transpose(v), split
    tsplit_k<<<dim3(D / 32, S / 32), blk>>>(vf, vThi, vTlo, S, D);

    // scores[h] = Q_h @ K_h^T  (fp32 out)
    {
        dim3 grid(S / 64, S / 128, H);
        gemm3_k<false, false, false><<<grid, blk>>>(qhi, qlo, khi, klo, nullptr,
            sc, nullptr, nullptr, DH, D, D, S, DH, DH, (long long)S * S);
    }

    // masked softmax -> P hi/lo
    softmax_mask_split_k<<<dim3(S, H), blk>>>(sc, mask, Phi, Plo);

    // attn_h = P_h @ V_h^T(T) : BT = vT rows [h*DH .. ), split-out
    {
        dim3 grid(1, S / 128, H);
        gemm3_k<false, false, true><<<grid, blk>>>(Phi, Plo, vThi, vTlo, nullptr,
            nullptr, attnhi, attnlo, S, S, S, D,
            (long long)S * S, (long long)DH * S, DH);
    }

    // output projection -> fp32 proj
    {
        dim3 grid(D / 64, S / 128, 1);
        gemm3_k<true, false, false><<<grid, blk>>>(attnhi, attnlo, woThi, woTlo, bo,
            proj, nullptr, nullptr, D, D, D, D, 0, 0, 0);
    }

    // x1 = LN(x + proj), with split
    add_ln_k<true><<<S, blk>>>(x, proj, g1, be1, x1, x1hi, x1lo);

    // ff = relu(x1 @ w1 + b1), split-out
    {
        dim3 grid(F / 64, S / 128, 1);
        gemm3_k<true, true, true><<<grid, blk>>>(x1hi, x1lo, w1Thi, w1Tlo, b1,
            nullptr, ffhi, fflo, D, D, D, F, 0, 0, 0);
    }

    // ff2 = ff @ w2 + b2 -> fp32 proj (reuse)
    {
        dim3 grid(D / 64, S / 128, 1);
        gemm3_k<true, false, false><<<grid, blk>>>(ffhi, fflo, w2Thi, w2Tlo, b2,
            proj, nullptr, nullptr, F, F, F, D, 0, 0, 0);
    }

    // out = LN(x1 + ff2)
    add_ln_k<false><<<S, blk>>>(x1, proj, g2, be2, out, nullptr, nullptr);
}

// round 4
// speedup vs baseline: 2.6184x; 1.3570x over previous
#include <cuda_runtime.h>
#include <cuda_bf16.h>
#include <math.h>

#define S 4096
#define D 512
#define F 2048
#define H 8
#define DH 64
#define EPS 1e-5f

typedef __nv_bfloat16 bf;

// ---------------- scratch (static device globals) ---------------------------
__device__ bf g_xhi[S * D], g_xlo[S * D];
__device__ bf g_wqThi[D * D], g_wqTlo[D * D];
__device__ bf g_wkThi[D * D], g_wkTlo[D * D];
__device__ bf g_wvThi[D * D], g_wvTlo[D * D];
__device__ bf g_woThi[D * D], g_woTlo[D * D];
__device__ bf g_w1Thi[(size_t)F * D], g_w1Tlo[(size_t)F * D];
__device__ bf g_w2Thi[(size_t)D * F], g_w2Tlo[(size_t)D * F];
__device__ bf g_qhi[S * D], g_qlo[S * D];
__device__ bf g_khi[S * D], g_klo[S * D];
__device__ float g_vf[S * D];
__device__ bf g_vThi[(size_t)D * S], g_vTlo[(size_t)D * S];
__device__ unsigned g_mb[(size_t)S * (S / 32)];
__device__ bf g_attnhi[S * D], g_attnlo[S * D];
__device__ float g_proj[S * D];
__device__ float g_x1[S * D];
__device__ bf g_x1hi[S * D], g_x1lo[S * D];
__device__ bf g_ffhi[(size_t)S * F], g_fflo[(size_t)S * F];

// ---------------- helpers ----------------------------------------------------
__device__ __forceinline__ void split2(float v, bf& h, bf& l) {
    h = __float2bfloat16(v);
    l = __float2bfloat16(v - __bfloat162float(h));
}

#define MMA_BF16(c, a, b) asm volatile( \
    "mma.sync.aligned.m16n8k16.row.col.f32.bf16.bf16.f32 " \
    "{%0,%1,%2,%3}, {%4,%5,%6,%7}, {%8,%9}, {%0,%1,%2,%3};\n" \
    : "+f"((c)[0]), "+f"((c)[1]), "+f"((c)[2]), "+f"((c)[3]) \
    : "r"((a)[0]), "r"((a)[1]), "r"((a)[2]), "r"((a)[3]), \
      "r"((b)[0]), "r"((b)[1]))

__device__ __forceinline__ unsigned pack_hi(float a, float b) {
    __nv_bfloat162 p;
    p.x = __float2bfloat16(a); p.y = __float2bfloat16(b);
    return *(unsigned*)&p;
}
__device__ __forceinline__ unsigned pack_lo(float a, float b) {
    bf ha = __float2bfloat16(a), hb = __float2bfloat16(b);
    __nv_bfloat162 p;
    p.x = __float2bfloat16(a - __bfloat162float(ha));
    p.y = __float2bfloat16(b - __bfloat162float(hb));
    return *(unsigned*)&p;
}

// ---------------- split fp32 -> (hi, lo) bf16 --------------------------------
__global__ void __launch_bounds__(256) split_k(
    const float4* __restrict__ in, __nv_bfloat162* __restrict__ hi2,
    __nv_bfloat162* __restrict__ lo2, int n4)
{
    int i = blockIdx.x * 256 + threadIdx.x;
    if (i >= n4) return;
    float4 v = in[i];
    bf hx, lx, hy, ly, hz, lz, hw, lw;
    split2(v.x, hx, lx); split2(v.y, hy, ly);
    split2(v.z, hz, lz); split2(v.w, hw, lw);
    __nv_bfloat162 a, b;
    a.x = hx; a.y = hy; b.x = hz; b.y = hw;
    hi2[2 * i] = a; hi2[2 * i + 1] = b;
    a.x = lx; a.y = ly; b.x = lz; b.y = lw;
    lo2[2 * i] = a; lo2[2 * i + 1] = b;
}

// ---------------- transpose + split: in[R][C] fp32 -> out[C][R] hi/lo --------
__global__ void __launch_bounds__(256) tsplit_k(
    const float* __restrict__ in, bf* __restrict__ hi, bf* __restrict__ lo,
    int R, int C)
{
    __shared__ float tile[32][33];
    const int c0 = blockIdx.x * 32, r0 = blockIdx.y * 32;
    const int tx = threadIdx.x & 31, ty = threadIdx.x >> 5;
#pragma unroll
    for (int rr = ty; rr < 32; rr += 8)
        tile[rr][tx] = in[(long long)(r0 + rr) * C + c0 + tx];
    __syncthreads();
#pragma unroll
    for (int cc = ty; cc < 32; cc += 8) {
        float v = tile[tx][cc];
        bf h, l; split2(v, h, l);
        long long o = (long long)(c0 + cc) * R + r0 + tx;
        hi[o] = h; lo[o] = l;
    }
}

// ---------------- pack mask to bits ------------------------------------------
__global__ void __launch_bounds__(1024) maskbits_k(
    const int* __restrict__ mask, unsigned* __restrict__ mb)
{
    const int row = blockIdx.x;
    const int warp = threadIdx.x >> 5, lane = threadIdx.x & 31;
#pragma unroll
    for (int w = warp; w < S / 32; w += 32) {
        int v = mask[(size_t)row * S + w * 32 + lane];
        unsigned bits = __ballot_sync(0xffffffffu, v != 0);
        if (lane == 0) mb[(size_t)row * (S / 32) + w] = bits;
    }
}

// ---------------- fused flash attention (bf16x3, online softmax) -------------
// grid (S/64, H), block 128 (4 warps x 16 rows). Key tiles of 64.
__global__ void __launch_bounds__(128) flash_k(
    const bf* __restrict__ qhi, const bf* __restrict__ qlo,
    const bf* __restrict__ khi, const bf* __restrict__ klo,
    const bf* __restrict__ vThi, const bf* __restrict__ vTlo,
    const unsigned* __restrict__ mb,
    bf* __restrict__ attnhi, bf* __restrict__ attnlo)
{
    extern __shared__ bf sm[];
    bf* Qh = sm;
    bf* Ql = Qh + 64 * 72;
    bf* Kh = Ql + 64 * 72;
    bf* Kl = Kh + 64 * 72;
    bf* Vh = Kl + 64 * 72;
    bf* Vl = Vh + 64 * 72;

    const int head = blockIdx.y;
    const int m0 = blockIdx.x * 64;
    const int t = threadIdx.x;
    const int lane = t & 31, warp = t >> 5;
    const int g = lane >> 2, c = lane & 3;
    const int wr = warp * 16;

    // load Q tile (64 rows x 64 cols) hi/lo
#pragma unroll
    for (int p = 0; p < 4; p++) {
        const int i = t + p * 128;
        const int r = i >> 3, cc = (i & 7) * 8;
        const long long go = (long long)(m0 + r) * D + head * DH + cc;
        *(uint4*)&Qh[r * 72 + cc] = *(const uint4*)&qhi[go];
        *(uint4*)&Ql[r * 72 + cc] = *(const uint4*)&qlo[go];
    }

    float oacc[8][4];
#pragma unroll
    for (int j = 0; j < 8; j++)
#pragma unroll
        for (int r = 0; r < 4; r++) oacc[j][r] = 0.f;
    float mrow0 = -3e38f, mrow1 = -3e38f;
    float lrow0 = 0.f, lrow1 = 0.f;

    const int row0 = m0 + wr + g;
    const int row1 = row0 + 8;
    const unsigned* mbr0 = mb + (size_t)row0 * (S / 32);
    const unsigned* mbr1 = mb + (size_t)row1 * (S / 32);

    __syncthreads();

    for (int t0 = 0; t0 < S; t0 += 64) {
        // load K tile (64 keys x 64 dh) and V^T tile (64 dh x 64 keys)
#pragma unroll
        for (int p = 0; p < 4; p++) {
            const int i = t + p * 128;
            const int r = i >> 3, cc = (i & 7) * 8;
            const long long gk = (long long)(t0 + r) * D + head * DH + cc;
            *(uint4*)&Kh[r * 72 + cc] = *(const uint4*)&khi[gk];
            *(uint4*)&Kl[r * 72 + cc] = *(const uint4*)&klo[gk];
            const long long gv = (long long)(head * DH + r) * S + t0 + cc;
            *(uint4*)&Vh[r * 72 + cc] = *(const uint4*)&vThi[gv];
            *(uint4*)&Vl[r * 72 + cc] = *(const uint4*)&vTlo[gv];
        }
        __syncthreads();

        // S = Q K^T (bf16x3)
        float sacc[8][4];
#pragma unroll
        for (int j = 0; j < 8; j++)
#pragma unroll
            for (int r = 0; r < 4; r++) sacc[j][r] = 0.f;

#pragma unroll
        for (int ks = 0; ks < 4; ks++) {
            const int kb = ks * 16 + c * 2;
            unsigned ah[4], al[4];
            ah[0] = *(const unsigned*)&Qh[(wr + g) * 72 + kb];
            ah[1] = *(const unsigned*)&Qh[(wr + g + 8) * 72 + kb];
            ah[2] = *(const unsigned*)&Qh[(wr + g) * 72 + kb + 8];
            ah[3] = *(const unsigned*)&Qh[(wr + g + 8) * 72 + kb + 8];
            al[0] = *(const unsigned*)&Ql[(wr + g) * 72 + kb];
            al[1] = *(const unsigned*)&Ql[(wr + g + 8) * 72 + kb];
            al[2] = *(const unsigned*)&Ql[(wr + g) * 72 + kb + 8];
            al[3] = *(const unsigned*)&Ql[(wr + g + 8) * 72 + kb + 8];
#pragma unroll
            for (int j = 0; j < 8; j++) {
                const int nr = j * 8 + g;
                unsigned bh[2], bl[2];
                bh[0] = *(const unsigned*)&Kh[nr * 72 + kb];
                bh[1] = *(const unsigned*)&Kh[nr * 72 + kb + 8];
                bl[0] = *(const unsigned*)&Kl[nr * 72 + kb];
                bl[1] = *(const unsigned*)&Kl[nr * 72 + kb + 8];
                MMA_BF16(sacc[j], ah, bh);
                MMA_BF16(sacc[j], ah, bl);
                MMA_BF16(sacc[j], al, bh);
            }
        }

        // mask (bit-packed)
        const unsigned w00 = mbr0[t0 / 32], w01 = mbr0[t0 / 32 + 1];
        const unsigned w10 = mbr1[t0 / 32], w11 = mbr1[t0 / 32 + 1];
#pragma unroll
        for (int j = 0; j < 8; j++) {
            const int col = j * 8 + c * 2;
            const unsigned wa0 = (col < 32) ? w00 : w01;
            const unsigned wa1 = (col < 32) ? w10 : w11;
            const int sh = col & 31;
            if (!((wa0 >> sh) & 1u))       sacc[j][0] = -1e9f;
            if (!((wa0 >> (sh + 1)) & 1u)) sacc[j][1] = -1e9f;
            if (!((wa1 >> sh) & 1u))       sacc[j][2] = -1e9f;
            if (!((wa1 >> (sh + 1)) & 1u)) sacc[j][3] = -1e9f;
        }

        // online softmax: row max
        float mt0 = -3e38f, mt1 = -3e38f;
#pragma unroll
        for (int j = 0; j < 8; j++) {
            mt0 = fmaxf(mt0, fmaxf(sacc[j][0], sacc[j][1]));
            mt1 = fmaxf(mt1, fmaxf(sacc[j][2], sacc[j][3]));
        }
        mt0 = fmaxf(mt0, __shfl_xor_sync(0xffffffffu, mt0, 1));
        mt0 = fmaxf(mt0, __shfl_xor_sync(0xffffffffu, mt0, 2));
        mt1 = fmaxf(mt1, __shfl_xor_sync(0xffffffffu, mt1, 1));
        mt1 = fmaxf(mt1, __shfl_xor_sync(0xffffffffu, mt1, 2));

        const float mn0 = fmaxf(mrow0, mt0);
        const float mn1 = fmaxf(mrow1, mt1);
        const float cf0 = __expf(mrow0 - mn0);
        const float cf1 = __expf(mrow1 - mn1);
        mrow0 = mn0; mrow1 = mn1;

        float rs0 = 0.f, rs1 = 0.f;
#pragma unroll
        for (int j = 0; j < 8; j++) {
            sacc[j][0] = __expf(sacc[j][0] - mn0);
            sacc[j][1] = __expf(sacc[j][1] - mn0);
            sacc[j][2] = __expf(sacc[j][2] - mn1);
            sacc[j][3] = __expf(sacc[j][3] - mn1);
            rs0 += sacc[j][0] + sacc[j][1];
            rs1 += sacc[j][2] + sacc[j][3];
        }
        rs0 += __shfl_xor_sync(0xffffffffu, rs0, 1);
        rs0 += __shfl_xor_sync(0xffffffffu, rs0, 2);
        rs1 += __shfl_xor_sync(0xffffffffu, rs1, 1);
        rs1 += __shfl_xor_sync(0xffffffffu, rs1, 2);
        lrow0 = lrow0 * cf0 + rs0;
        lrow1 = lrow1 * cf1 + rs1;

#pragma unroll
        for (int j = 0; j < 8; j++) {
            oacc[j][0] *= cf0; oacc[j][1] *= cf0;
            oacc[j][2] *= cf1; oacc[j][3] *= cf1;
        }

        // pack P to bf16 hi/lo A-fragments (accumulator layout == A layout)
        unsigned phi[4][4], plo[4][4];
#pragma unroll
        for (int ks = 0; ks < 4; ks++) {
            phi[ks][0] = pack_hi(sacc[2 * ks][0], sacc[2 * ks][1]);
            phi[ks][1] = pack_hi(sacc[2 * ks][2], sacc[2 * ks][3]);
            phi[ks][2] = pack_hi(sacc[2 * ks + 1][0], sacc[2 * ks + 1][1]);
            phi[ks][3] = pack_hi(sacc[2 * ks + 1][2], sacc[2 * ks + 1][3]);
            plo[ks][0] = pack_lo(sacc[2 * ks][0], sacc[2 * ks][1]);
            plo[ks][1] = pack_lo(sacc[2 * ks][2], sacc[2 * ks][3]);
            plo[ks][2] = pack_lo(sacc[2 * ks + 1][0], sacc[2 * ks + 1][1]);
            plo[ks][3] = pack_lo(sacc[2 * ks + 1][2], sacc[2 * ks + 1][3]);
        }

        // O += P V (bf16x3)
#pragma unroll
        for (int ks = 0; ks < 4; ks++) {
            const int kb = ks * 16 + c * 2;
#pragma unroll
            for (int j = 0; j < 8; j++) {
                const int nr = j * 8 + g;
                unsigned vh[2], vl[2];
                vh[0] = *(const unsigned*)&Vh[nr * 72 + kb];
                vh[1] = *(const unsigned*)&Vh[nr * 72 + kb + 8];
                vl[0] = *(const unsigned*)&Vl[nr * 72 + kb];
                vl[1] = *(const unsigned*)&Vl[nr * 72 + kb + 8];
                MMA_BF16(oacc[j], phi[ks], vh);
                MMA_BF16(oacc[j], phi[ks], vl);
                MMA_BF16(oacc[j], plo[ks], vh);
            }
        }
        __syncthreads();
    }

    // epilogue: normalize, split, store
    const float inv0 = 1.f / lrow0;
    const float inv1 = 1.f / lrow1;
#pragma unroll
    for (int j = 0; j < 8; j++) {
        const int col = head * DH + j * 8 + c * 2;
        float v0 = oacc[j][0] * inv0, v1 = oacc[j][1] * inv0;
        float v2 = oacc[j][2] * inv1, v3 = oacc[j][3] * inv1;
        bf h0, l0, h1, l1;
        split2(v0, h0, l0); split2(v1, h1, l1);
        __nv_bfloat162 ph, pl;
        ph.x = h0; ph.y = h1; pl.x = l0; pl.y = l1;
        *(__nv_bfloat162*)&attnhi[(size_t)row0 * D + col] = ph;
        *(__nv_bfloat162*)&attnlo[(size_t)row0 * D + col] = pl;
        split2(v2, h0, l0); split2(v3, h1, l1);
        ph.x = h0; ph.y = h1; pl.x = l0; pl.y = l1;
        *(__nv_bfloat162*)&attnhi[(size_t)row1 * D + col] = ph;
        *(__nv_bfloat162*)&attnlo[(size_t)row1 * D + col] = pl;
    }
}

// ---------------- bf16x3 tensor-core GEMM (NT form) --------------------------
template <bool HASBIAS, bool RELU, bool SPLITOUT>
__global__ void __launch_bounds__(256) gemm3_k(
    const bf* __restrict__ Ahi, const bf* __restrict__ Alo,
    const bf* __restrict__ Bhi, const bf* __restrict__ Blo,
    const float* __restrict__ bias,
    float* __restrict__ C, bf* __restrict__ Chi, bf* __restrict__ Clo,
    int K, int lda, int ldb, int ldc,
    long long aOff, long long bOff, long long cOff)
{
    const int bz = blockIdx.z;
    Ahi += (long long)bz * aOff; Alo += (long long)bz * aOff;
    Bhi += (long long)bz * bOff; Blo += (long long)bz * bOff;
    const long long cbase = (long long)bz * cOff;

    const int m0 = blockIdx.y * 128;
    const int n0 = blockIdx.x * 64;
    const int t = threadIdx.x;
    const int lane = t & 31, warp = t >> 5;
    const int g = lane >> 2, ctid = lane & 3;
    const int wm = (warp & 3) * 32;
    const int wn = (warp >> 2) * 32;

    __shared__ __align__(16) bf Ahs[128 * 40];
    __shared__ __align__(16) bf Als[128 * 40];
    __shared__ __align__(16) bf Bhs[64 * 40];
    __shared__ __align__(16) bf Bls[64 * 40];

    float acc[2][4][4];
#pragma unroll
    for (int i = 0; i < 2; i++)
#pragma unroll
        for (int j = 0; j < 4; j++)
#pragma unroll
            for (int r = 0; r < 4; r++) acc[i][j][r] = 0.f;

    const int ar = t >> 2;
    const int ac = (t & 3) * 8;

    for (int k0 = 0; k0 < K; k0 += 32) {
        const bf* pAh = Ahi + (long long)(m0 + ar) * lda + k0 + ac;
        const bf* pAl = Alo + (long long)(m0 + ar) * lda + k0 + ac;
        *(uint4*)&Ahs[ar * 40 + ac] = *(const uint4*)pAh;
        *(uint4*)&Als[ar * 40 + ac] = *(const uint4*)pAl;
        *(uint4*)&Ahs[(ar + 64) * 40 + ac] = *(const uint4*)(pAh + (long long)64 * lda);
        *(uint4*)&Als[(ar + 64) * 40 + ac] = *(const uint4*)(pAl + (long long)64 * lda);
        *(uint4*)&Bhs[ar * 40 + ac] = *(const uint4*)(Bhi + (long long)(n0 + ar) * ldb + k0 + ac);
        *(uint4*)&Bls[ar * 40 + ac] = *(const uint4*)(Blo + (long long)(n0 + ar) * ldb + k0 + ac);
        __syncthreads();

#pragma unroll
        for (int ks = 0; ks < 2; ks++) {
            const int kb = ks * 16 + ctid * 2;
            unsigned int ah[2][4], al[2][4], bh[4][2], bl[4][2];
#pragma unroll
            for (int i = 0; i < 2; i++) {
                const int row = wm + i * 16 + g;
                ah[i][0] = *(const unsigned int*)&Ahs[row * 40 + kb];
                ah[i][1] = *(const unsigned int*)&Ahs[(row + 8) * 40 + kb];
                ah[i][2] = *(const unsigned int*)&Ahs[row * 40 + kb + 8];
                ah[i][3] = *(const unsigned int*)&Ahs[(row + 8) * 40 + kb + 8];
                al[i][0] = *(const unsigned int*)&Als[row * 40 + kb];
                al[i][1] = *(const unsigned int*)&Als[(row + 8) * 40 + kb];
                al[i][2] = *(const unsigned int*)&Als[row * 40 + kb + 8];
                al[i][3] = *(const unsigned int*)&Als[(row + 8) * 40 + kb + 8];
            }
#pragma unroll
            for (int j = 0; j < 4; j++) {
                const int nr = wn + j * 8 + g;
                bh[j][0] = *(const unsigned int*)&Bhs[nr * 40 + kb];
                bh[j][1] = *(const unsigned int*)&Bhs[nr * 40 + kb + 8];
                bl[j][0] = *(const unsigned int*)&Bls[nr * 40 + kb];
                bl[j][1] = *(const unsigned int*)&Bls[nr * 40 + kb + 8];
            }
#pragma unroll
            for (int i = 0; i < 2; i++)
#pragma unroll
                for (int j = 0; j < 4; j++) {
                    MMA_BF16(acc[i][j], ah[i], bh[j]);
                    MMA_BF16(acc[i][j], ah[i], bl[j]);
                    MMA_BF16(acc[i][j], al[i], bh[j]);
                }
        }
        __syncthreads();
    }

#pragma unroll
    for (int i = 0; i < 2; i++) {
#pragma unroll
        for (int j = 0; j < 4; j++) {
            const int row0 = m0 + wm + i * 16 + g;
            const int col = n0 + wn + j * 8 + ctid * 2;
            float bia0 = 0.f, bia1 = 0.f;
            if (HASBIAS) { bia0 = bias[col]; bia1 = bias[col + 1]; }
#pragma unroll
            for (int hh = 0; hh < 2; hh++) {
                const int row = row0 + hh * 8;
                float v0 = acc[i][j][hh * 2 + 0] + bia0;
                float v1 = acc[i][j][hh * 2 + 1] + bia1;
                if (RELU) { v0 = fmaxf(v0, 0.f); v1 = fmaxf(v1, 0.f); }
                const long long o = cbase + (long long)row * ldc + col;
                if (SPLITOUT) {
                    bf h0, l0, h1, l1;
                    split2(v0, h0, l0); split2(v1, h1, l1);
                    __nv_bfloat162 ph, pl;
                    ph.x = h0; ph.y = h1; pl.x = l0; pl.y = l1;
                    *(__nv_bfloat162*)&Chi[o] = ph;
                    *(__nv_bfloat162*)&Clo[o] = pl;
                } else {
                    *(float2*)&C[o] = make_float2(v0, v1);
                }
            }
        }
    }
}

// ---------------- fused residual add + LayerNorm (+optional split) -----------
template <bool SPLIT>
__global__ void __launch_bounds__(256) add_ln_k(
    const float* __restrict__ x, const float* __restrict__ r,
    const float* __restrict__ g, const float* __restrict__ b,
    float* __restrict__ y, bf* __restrict__ yhi, bf* __restrict__ ylo)
{
    const int row = blockIdx.x;
    const int t = threadIdx.x;
    const long long base = (long long)row * D;

    float v0 = x[base + t] + r[base + t];
    float v1 = x[base + t + 256] + r[base + t + 256];

    float s = v0 + v1;
    float s2 = v0 * v0 + v1 * v1;

    __shared__ float rs[8], rs2[8];
#pragma unroll
    for (int o = 16; o > 0; o >>= 1) {
        s += __shfl_xor_sync(0xffffffffu, s, o);
        s2 += __shfl_xor_sync(0xffffffffu, s2, o);
    }
    if ((t & 31) == 0) { rs[t >> 5] = s; rs2[t >> 5] = s2; }
    __syncthreads();
    if (t < 8) {
        float a = rs[t], c = rs2[t];
#pragma unroll
        for (int o = 4; o > 0; o >>= 1) {
            a += __shfl_xor_sync(0xffu, a, o);
            c += __shfl_xor_sync(0xffu, c, o);
        }
        if (t == 0) { rs[0] = a; rs2[0] = c; }
    }
    __syncthreads();
    const float mu = rs[0] * (1.f / D);
    const float var = rs2[0] * (1.f / D) - mu * mu;
    const float rstd = rsqrtf(var + EPS);

    float y0 = (v0 - mu) * rstd * g[t] + b[t];
    float y1 = (v1 - mu) * rstd * g[t + 256] + b[t + 256];
    y[base + t] = y0;
    y[base + t + 256] = y1;
    if (SPLIT) {
        bf h0, l0, h1, l1;
        split2(y0, h0, l0); split2(y1, h1, l1);
        yhi[base + t] = h0; ylo[base + t] = l0;
        yhi[base + t + 256] = h1; ylo[base + t + 256] = l1;
    }
}

// ---------------- launch -----------------------------------------------------
extern "C" void kernel_launch(void* const* d_in, const int* in_sizes, int n_in,
                              void* d_out, int out_size)
{
    const float* x   = (const float*)d_in[0];
    const int* mask  = (const int*)d_in[1];
    const float* wq  = (const float*)d_in[2];
    const float* bq  = (const float*)d_in[3];
    const float* wk  = (const float*)d_in[4];
    const float* bk  = (const float*)d_in[5];
    const float* wv  = (const float*)d_in[6];
    const float* bv  = (const float*)d_in[7];
    const float* wo  = (const float*)d_in[8];
    const float* bo  = (const float*)d_in[9];
    const float* w1  = (const float*)d_in[10];
    const float* b1  = (const float*)d_in[11];
    const float* w2  = (const float*)d_in[12];
    const float* b2  = (const float*)d_in[13];
    const float* g1  = (const float*)d_in[14];
    const float* be1 = (const float*)d_in[15];
    const float* g2  = (const float*)d_in[16];
    const float* be2 = (const float*)d_in[17];
    float* out = (float*)d_out;

    bf *xhi, *xlo, *wqThi, *wqTlo, *wkThi, *wkTlo, *wvThi, *wvTlo, *woThi, *woTlo;
    bf *w1Thi, *w1Tlo, *w2Thi, *w2Tlo, *qhi, *qlo, *khi, *klo, *vThi, *vTlo;
    bf *attnhi, *attnlo, *x1hi, *x1lo, *ffhi, *fflo;
    float *vf, *proj, *x1;
    unsigned* mb;
    cudaGetSymbolAddress((void**)&xhi, g_xhi);   cudaGetSymbolAddress((void**)&xlo, g_xlo);
    cudaGetSymbolAddress((void**)&wqThi, g_wqThi); cudaGetSymbolAddress((void**)&wqTlo, g_wqTlo);
    cudaGetSymbolAddress((void**)&wkThi, g_wkThi); cudaGetSymbolAddress((void**)&wkTlo, g_wkTlo);
    cudaGetSymbolAddress((void**)&wvThi, g_wvThi); cudaGetSymbolAddress((void**)&wvTlo, g_wvTlo);
    cudaGetSymbolAddress((void**)&woThi, g_woThi); cudaGetSymbolAddress((void**)&woTlo, g_woTlo);
    cudaGetSymbolAddress((void**)&w1Thi, g_w1Thi); cudaGetSymbolAddress((void**)&w1Tlo, g_w1Tlo);
    cudaGetSymbolAddress((void**)&w2Thi, g_w2Thi); cudaGetSymbolAddress((void**)&w2Tlo, g_w2Tlo);
    cudaGetSymbolAddress((void**)&qhi, g_qhi);   cudaGetSymbolAddress((void**)&qlo, g_qlo);
    cudaGetSymbolAddress((void**)&khi, g_khi);   cudaGetSymbolAddress((void**)&klo, g_klo);
    cudaGetSymbolAddress((void**)&vf, g_vf);
    cudaGetSymbolAddress((void**)&vThi, g_vThi); cudaGetSymbolAddress((void**)&vTlo, g_vTlo);
    cudaGetSymbolAddress((void**)&mb, g_mb);
    cudaGetSymbolAddress((void**)&attnhi, g_attnhi); cudaGetSymbolAddress((void**)&attnlo, g_attnlo);
    cudaGetSymbolAddress((void**)&proj, g_proj);
    cudaGetSymbolAddress((void**)&x1, g_x1);
    cudaGetSymbolAddress((void**)&x1hi, g_x1hi); cudaGetSymbolAddress((void**)&x1lo, g_x1lo);
    cudaGetSymbolAddress((void**)&ffhi, g_ffhi); cudaGetSymbolAddress((void**)&fflo, g_fflo);

    const dim3 blk(256);
    const int FLASH_SMEM = 6 * 64 * 72 * (int)sizeof(bf);
    cudaFuncSetAttribute(flash_k, cudaFuncAttributeMaxDynamicSharedMemorySize, FLASH_SMEM);

    // split x; pack mask bits
    split_k<<<(S * D / 4 + 255) / 256, blk>>>((const float4*)x,
        (__nv_bfloat162*)xhi, (__nv_bfloat162*)xlo, S * D / 4);
    maskbits_k<<<S, 1024>>>(mask, mb);

    // transpose + split weights
    tsplit_k<<<dim3(D / 32, D / 32), blk>>>(wq, wqThi, wqTlo, D, D);
    tsplit_k<<<dim3(D / 32, D / 32), blk>>>(wk, wkThi, wkTlo, D, D);
    tsplit_k<<<dim3(D / 32, D / 32), blk>>>(wv, wvThi, wvTlo, D, D);
    tsplit_k<<<dim3(D / 32, D / 32), blk>>>(wo, woThi, woTlo, D, D);
    tsplit_k<<<dim3(F / 32, D / 32), blk>>>(w1, w1Thi, w1Tlo, D, F);
    tsplit_k<<<dim3(D / 32, F / 32), blk>>>(w2, w2Thi, w2Tlo, F, D);

    // QKV projections
    {
        dim3 grid(D / 64, S / 128, 1);
        gemm3_k<true, false, true><<<grid, blk>>>(xhi, xlo, wqThi, wqTlo, bq,
            nullptr, qhi, qlo, D, D, D, D, 0, 0, 0);
        gemm3_k<true, false, true><<<grid, blk>>>(xhi, xlo, wkThi, wkTlo, bk,
            nullptr, khi, klo, D, D, D, D, 0, 0, 0);
        gemm3_k<true, false, false><<<grid, blk>>>(xhi, xlo, wvThi, wvTlo, bv,
            vf, nullptr, nullptr, D, D, D, D, 0, 0, 0);
    }

    // vT = transpose(v), split
    tsplit_k<<<dim3(D / 32, S / 32), blk>>>(vf, vThi, vTlo, S, D);

    // fused attention
    flash_k<<<dim3(S / 64, H), 128, FLASH_SMEM>>>(qhi, qlo, khi, klo,
        vThi, vTlo, mb, attnhi, attnlo);

    // output projection
    {
        dim3 grid(D / 64, S / 128, 1);
        gemm3_k<true, false, false><<<grid, blk>>>(attnhi, attnlo, woThi, woTlo, bo,
            proj, nullptr, nullptr, D, D, D, D, 0, 0, 0);
    }

    // x1 = LN(x + proj), with split
    add_ln_k<true><<<S, blk>>>(x, proj, g1, be1, x1, x1hi, x1lo);

    // ff = relu(x1 @ w1 + b1)
    {
        dim3 grid(F / 64, S / 128, 1);
        gemm3_k<true, true, true><<<grid, blk>>>(x1hi, x1lo, w1Thi, w1Tlo, b1,
            nullptr, ffhi, fflo, D, D, D, F, 0, 0, 0);
    }

    // ff2 = ff @ w2 + b2
    {
        dim3 grid(D / 64, S / 128, 1);
        gemm3_k<true, false, false><<<grid, blk>>>(ffhi, fflo, w2Thi, w2Tlo, b2,
            proj, nullptr, nullptr, F, F, F, D, 0, 0, 0);
    }

    // out = LN(x1 + ff2)
    add_ln_k<false><<<S, blk>>>(x1, proj, g2, be2, out, nullptr, nullptr);
}